// round 3
// baseline (speedup 1.0000x reference)
#include <cuda_runtime.h>
#include <cuda_bf16.h>

// LinearCRF: out = mean_b( logZ_b - gold_b )
// Linear-domain forward algorithm with exact power-of-2 renormalization.
// Row split into NCHUNK=16 chunks of 64 steps; each chunk thread accumulates
// the 3x3 linear transfer matrix (mask==0 -> identity step).
// Combine: alpha0 chained through 16 chunk matrices + logZ + block reduce.

#define B_DIM   8192
#define L_DIM   1024
#define NCHUNK  16
#define CLEN    64           // L_DIM / NCHUNK
#define NGROUP  16           // CLEN / 4
#define COMB_BLOCKS  32
#define COMB_THREADS 256
#define LN2F 0.69314718055994530942f

__device__ float g_scratch[NCHUNK * 12 * B_DIM];   // [(c*12+k)*B + b]
__device__ float g_partials[COMB_BLOCKS];

// One forward step in linear domain (matrix form):
//   Mnew[i][j] = (sum_k M[i][k] * E[k][j]) * w_j,   w_j = exp(em_t[j])
// mask <= 0  => keep M (identity step). gold accumulates trans+emission at tag.
#define STEP(e0v, e1v, e2v, tgv, mv) do {                                   \
    float w0 = __expf(e0v), w1 = __expf(e1v), w2 = __expf(e2v);             \
    float F00 = E00 * w0, F01 = E01 * w1, F02 = E02 * w2;                   \
    float F10 = E10 * w0, F11 = E11 * w1, F12 = E12 * w2;                   \
    float F20 = E20 * w0, F21 = E21 * w1, F22 = E22 * w2;                   \
    float n00 = fmaf(M02, F20, fmaf(M01, F10, M00 * F00));                  \
    float n01 = fmaf(M02, F21, fmaf(M01, F11, M00 * F01));                  \
    float n02 = fmaf(M02, F22, fmaf(M01, F12, M00 * F02));                  \
    float n10 = fmaf(M12, F20, fmaf(M11, F10, M10 * F00));                  \
    float n11 = fmaf(M12, F21, fmaf(M11, F11, M10 * F01));                  \
    float n12 = fmaf(M12, F22, fmaf(M11, F12, M10 * F02));                  \
    float n20 = fmaf(M22, F20, fmaf(M21, F10, M20 * F00));                  \
    float n21 = fmaf(M22, F21, fmaf(M21, F11, M20 * F01));                  \
    float n22 = fmaf(M22, F22, fmaf(M21, F12, M20 * F02));                  \
    bool u = (mv) > 0.f;                                                    \
    M00 = u ? n00 : M00; M01 = u ? n01 : M01; M02 = u ? n02 : M02;          \
    M10 = u ? n10 : M10; M11 = u ? n11 : M11; M12 = u ? n12 : M12;          \
    M20 = u ? n20 : M20; M21 = u ? n21 : M21; M22 = u ? n22 : M22;          \
    int tgl = (tgv);                                                        \
    float etg = (tgl == 0) ? (e0v) : ((tgl == 1) ? (e1v) : (e2v));          \
    float tr  = sT[ptag * 3 + tgl];                                         \
    gold = fmaf((mv), tr + etg, gold);                                      \
    ptag = tgl;                                                             \
} while (0)

__global__ void __launch_bounds__(128, 6)
crf_chunk_kernel(const float* __restrict__ emissions,
                 const float* __restrict__ mask,
                 const float* __restrict__ transitions,
                 const int*   __restrict__ tags)
{
    __shared__ float sT[9];
    if (threadIdx.x < 9) sT[threadIdx.x] = transitions[threadIdx.x];
    __syncthreads();

    unsigned gtid = blockIdx.x * blockDim.x + threadIdx.x;   // [0, 131072)
    unsigned b = gtid & (B_DIM - 1);
    unsigned c = gtid >> 13;                                  // chunk 0..15

    float E00 = __expf(sT[0]), E01 = __expf(sT[1]), E02 = __expf(sT[2]);
    float E10 = __expf(sT[3]), E11 = __expf(sT[4]), E12 = __expf(sT[5]);
    float E20 = __expf(sT[6]), E21 = __expf(sT[7]), E22 = __expf(sT[8]);

    // Row/chunk base pointers (16B aligned: CLEN*3*4 = 768B, CLEN*4 = 256B)
    const float4* em4 = (const float4*)emissions + (size_t)b * 768 + (size_t)c * 48;
    const int4*   tg4 = (const int4*)tags        + (size_t)b * 256 + (size_t)c * 16;
    const float4* mk4 = (const float4*)mask      + (size_t)b * 256 + (size_t)c * 16;

    int ptag = tags[(size_t)b * L_DIM + (c ? (int)(c * CLEN) - 1 : 0)];

    float M00 = 1.f, M01 = 0.f, M02 = 0.f;
    float M10 = 0.f, M11 = 1.f, M12 = 0.f;
    float M20 = 0.f, M21 = 0.f, M22 = 1.f;
    float gold = 0.f;
    int esum = 0;

    // prime double buffer (group 0)
    float4 eA0 = em4[0], eA1 = em4[1], eA2 = em4[2];
    int4   tA  = tg4[0];
    float4 mA  = mk4[0];
    if (c == 0) mA.x = 0.f;   // t==0 is the init step, not a transition

    #pragma unroll 1
    for (int g = 0; g < NGROUP; ++g) {
        float4 eB0 = eA0, eB1 = eA1, eB2 = eA2;
        int4   tB  = tA;
        float4 mB  = mA;
        if (g + 1 < NGROUP) {
            eB0 = em4[(g + 1) * 3 + 0];
            eB1 = em4[(g + 1) * 3 + 1];
            eB2 = em4[(g + 1) * 3 + 2];
            tB  = tg4[g + 1];
            mB  = mk4[g + 1];
        }

        STEP(eA0.x, eA0.y, eA0.z, tA.x, mA.x);
        STEP(eA0.w, eA1.x, eA1.y, tA.y, mA.y);
        STEP(eA1.z, eA1.w, eA2.x, tA.z, mA.z);
        STEP(eA2.y, eA2.z, eA2.w, tA.w, mA.w);

        // exact renormalization: scale by 2^-ex where ex = ilogb(max entry)
        float mxa = fmaxf(fmaxf(M00, M01), M02);
        float mxb = fmaxf(fmaxf(M10, M11), M12);
        float mxc = fmaxf(fmaxf(M20, M21), M22);
        float mx  = fmaxf(fmaxf(mxa, mxb), mxc);
        int ex = (__float_as_int(mx) >> 23) - 127;         // mx > 0 always
        float sc = __int_as_float((127 - ex) << 23);       // 2^-ex, exact
        M00 *= sc; M01 *= sc; M02 *= sc;
        M10 *= sc; M11 *= sc; M12 *= sc;
        M20 *= sc; M21 *= sc; M22 *= sc;
        esum += ex;

        eA0 = eB0; eA1 = eB1; eA2 = eB2; tA = tB; mA = mB;
    }

    // coalesced store: consecutive lanes -> consecutive b
    float* s = g_scratch + (size_t)c * 12 * B_DIM + b;
    s[0 * B_DIM] = M00; s[1 * B_DIM] = M01; s[2 * B_DIM] = M02;
    s[3 * B_DIM] = M10; s[4 * B_DIM] = M11; s[5 * B_DIM] = M12;
    s[6 * B_DIM] = M20; s[7 * B_DIM] = M21; s[8 * B_DIM] = M22;
    s[9 * B_DIM]  = (float)esum;
    s[10 * B_DIM] = gold;
}

__global__ void __launch_bounds__(COMB_THREADS)
crf_combine_kernel(const float* __restrict__ emissions,
                   const float* __restrict__ mask,
                   const int*   __restrict__ tags)
{
    int b = blockIdx.x * blockDim.x + threadIdx.x;   // [0, 8192)

    float4 e4 = ((const float4*)emissions)[(size_t)b * 768];   // em[b,0,0..2]
    float v0 = __expf(e4.x), v1 = __expf(e4.y), v2 = __expf(e4.z);

    int   tg0 = tags[(size_t)b * L_DIM];
    float m0  = mask[(size_t)b * L_DIM];
    float etg = (tg0 == 0) ? e4.x : ((tg0 == 1) ? e4.y : e4.z);
    float gold = etg * m0;
    float esum = 0.f;

    #pragma unroll
    for (int c = 0; c < NCHUNK; ++c) {
        const float* s = g_scratch + (size_t)c * 12 * B_DIM + b;
        float M00 = s[0 * B_DIM], M01 = s[1 * B_DIM], M02 = s[2 * B_DIM];
        float M10 = s[3 * B_DIM], M11 = s[4 * B_DIM], M12 = s[5 * B_DIM];
        float M20 = s[6 * B_DIM], M21 = s[7 * B_DIM], M22 = s[8 * B_DIM];
        esum += s[9 * B_DIM];
        gold += s[10 * B_DIM];

        float n0 = fmaf(v2, M20, fmaf(v1, M10, v0 * M00));
        float n1 = fmaf(v2, M21, fmaf(v1, M11, v0 * M01));
        float n2 = fmaf(v2, M22, fmaf(v1, M12, v0 * M02));

        float mx = fmaxf(fmaxf(n0, n1), n2);
        int ex = (__float_as_int(mx) >> 23) - 127;
        float sc = __int_as_float((127 - ex) << 23);
        v0 = n0 * sc; v1 = n1 * sc; v2 = n2 * sc;
        esum += (float)ex;
    }

    float logZ = __logf(v0 + v1 + v2) + esum * LN2F;
    float val  = logZ - gold;

    __shared__ float red[COMB_THREADS];
    red[threadIdx.x] = val;
    __syncthreads();
    #pragma unroll
    for (int s = COMB_THREADS / 2; s > 0; s >>= 1) {
        if (threadIdx.x < s) red[threadIdx.x] += red[threadIdx.x + s];
        __syncthreads();
    }
    if (threadIdx.x == 0) g_partials[blockIdx.x] = red[0];
}

__global__ void crf_final_kernel(float* __restrict__ out)
{
    float v = g_partials[threadIdx.x];   // 32 threads, 32 partials
    #pragma unroll
    for (int o = 16; o > 0; o >>= 1) v += __shfl_down_sync(0xffffffffu, v, o);
    if (threadIdx.x == 0) out[0] = v * (1.0f / (float)B_DIM);
}

extern "C" void kernel_launch(void* const* d_in, const int* in_sizes, int n_in,
                              void* d_out, int out_size)
{
    const float* emissions   = (const float*)d_in[0];
    const float* mask        = (const float*)d_in[1];
    const float* transitions = (const float*)d_in[2];
    const int*   tags        = (const int*)d_in[3];
    float* out = (float*)d_out;

    crf_chunk_kernel<<<(B_DIM * NCHUNK) / 128, 128>>>(emissions, mask, transitions, tags);
    crf_combine_kernel<<<COMB_BLOCKS, COMB_THREADS>>>(emissions, mask, tags);
    crf_final_kernel<<<1, 32>>>(out);
}

// round 4
// speedup vs baseline: 1.3367x; 1.3367x over previous
#include <cuda_runtime.h>
#include <cstdint>

// LinearCRF: out = mean_b( logZ_b - gold_b )
// Warp-per-row, lane-per-32-step-chunk. cp.async coalesced staging into
// conflict-free padded smem; linear-domain transfer matrices with exact
// pow2 renorm; in-warp shuffle tree combines the 32 chunk matrices.

#define B_DIM   8192
#define L_DIM   1024
#define RPB     4            // rows per block (1 per warp)
#define THREADS 128
#define NBLOCKS (B_DIM / RPB)   // 2048
#define LN2F 0.69314718055994530942f

// smem layout (padded for conflict-free LDS.128: lane stride 25 / 9 float4)
#define EM_ROW_F4 800        // 32 lanes * 25 slots (24 used)
#define TM_ROW_F4 288        // 32 lanes * 9 slots (8 used)
#define EM_BYTES  (RPB * EM_ROW_F4 * 16)         // 51200
#define TM_BYTES  (RPB * TM_ROW_F4 * 16)         // 18432
#define SMEM_BYTES (EM_BYTES + 2 * TM_BYTES)     // 88064

__device__ float g_partials[NBLOCKS];

__device__ __forceinline__ void cp16(uint32_t saddr, const void* gaddr) {
    asm volatile("cp.async.cg.shared.global [%0], [%1], 16;" :: "r"(saddr), "l"(gaddr));
}

// One forward step in linear domain (matrix form):
//   Mnew[i][j] = (sum_k M[i][k] * E[k][j]) * w_j,   w_j = exp(em_t[j])
// mask <= 0 => identity step. gold accumulates trans+emission at tag.
#define STEP(e0v, e1v, e2v, tgv, mv) do {                                   \
    float w0 = __expf(e0v), w1 = __expf(e1v), w2 = __expf(e2v);             \
    float F00 = E00 * w0, F01 = E01 * w1, F02 = E02 * w2;                   \
    float F10 = E10 * w0, F11 = E11 * w1, F12 = E12 * w2;                   \
    float F20 = E20 * w0, F21 = E21 * w1, F22 = E22 * w2;                   \
    float n00 = fmaf(M02, F20, fmaf(M01, F10, M00 * F00));                  \
    float n01 = fmaf(M02, F21, fmaf(M01, F11, M00 * F01));                  \
    float n02 = fmaf(M02, F22, fmaf(M01, F12, M00 * F02));                  \
    float n10 = fmaf(M12, F20, fmaf(M11, F10, M10 * F00));                  \
    float n11 = fmaf(M12, F21, fmaf(M11, F11, M10 * F01));                  \
    float n12 = fmaf(M12, F22, fmaf(M11, F12, M10 * F02));                  \
    float n20 = fmaf(M22, F20, fmaf(M21, F10, M20 * F00));                  \
    float n21 = fmaf(M22, F21, fmaf(M21, F11, M20 * F01));                  \
    float n22 = fmaf(M22, F22, fmaf(M21, F12, M20 * F02));                  \
    bool u = (mv) > 0.f;                                                    \
    M00 = u ? n00 : M00; M01 = u ? n01 : M01; M02 = u ? n02 : M02;          \
    M10 = u ? n10 : M10; M11 = u ? n11 : M11; M12 = u ? n12 : M12;          \
    M20 = u ? n20 : M20; M21 = u ? n21 : M21; M22 = u ? n22 : M22;          \
    int tgl = (tgv);                                                        \
    float etg = (tgl == 0) ? (e0v) : ((tgl == 1) ? (e1v) : (e2v));          \
    float tr  = sT[ptag * 3 + tgl];                                         \
    gold = fmaf((mv), tr + etg, gold);                                      \
    ptag = tgl;                                                             \
} while (0)

__global__ void __launch_bounds__(THREADS)
crf_main_kernel(const float* __restrict__ emissions,
                const float* __restrict__ mask,
                const float* __restrict__ transitions,
                const int*   __restrict__ tags)
{
    extern __shared__ char smem[];
    float4* emS = (float4*)smem;
    int4*   tgS = (int4*)(smem + EM_BYTES);
    float4* mkS = (float4*)(smem + EM_BYTES + TM_BYTES);
    __shared__ float sT[9];
    __shared__ float sred[RPB];

    const int tid  = threadIdx.x;
    const int lane = tid & 31;
    const int w    = tid >> 5;                 // warp id == local row
    const int row0 = blockIdx.x * RPB;

    if (tid < 9) sT[tid] = transitions[tid];

    uint32_t emS_a = (uint32_t)__cvta_generic_to_shared(emS);
    uint32_t tgS_a = (uint32_t)__cvta_generic_to_shared(tgS);
    uint32_t mkS_a = (uint32_t)__cvta_generic_to_shared(mkS);

    const float4* emG = (const float4*)emissions + (size_t)row0 * 768;
    const int4*   tgG = (const int4*)tags        + (size_t)row0 * 256;
    const float4* mkG = (const float4*)mask      + (size_t)row0 * 256;

    // ---- coalesced staging (gmem linear -> padded smem) ----
    #pragma unroll
    for (int r = 0; r < RPB; ++r) {
        #pragma unroll
        for (int i = 0; i < 6; ++i) {
            int k = tid + i * THREADS;                 // 0..767
            int owner = k / 24, slot = k - owner * 24;
            cp16(emS_a + (uint32_t)((r * EM_ROW_F4 + owner * 25 + slot) * 16),
                 emG + (size_t)r * 768 + k);
        }
        #pragma unroll
        for (int i = 0; i < 2; ++i) {
            int k = tid + i * THREADS;                 // 0..255
            int owner = k >> 3, slot = k & 7;
            uint32_t off = (uint32_t)((r * TM_ROW_F4 + owner * 9 + slot) * 16);
            cp16(tgS_a + off, tgG + (size_t)r * 256 + k);
            cp16(mkS_a + off, mkG + (size_t)r * 256 + k);
        }
    }
    asm volatile("cp.async.commit_group;");
    asm volatile("cp.async.wait_group 0;");
    __syncthreads();

    float E00 = __expf(sT[0]), E01 = __expf(sT[1]), E02 = __expf(sT[2]);
    float E10 = __expf(sT[3]), E11 = __expf(sT[4]), E12 = __expf(sT[5]);
    float E20 = __expf(sT[6]), E21 = __expf(sT[7]), E22 = __expf(sT[8]);

    // ---- per-lane chunk of 32 steps from smem ----
    const float4* em = emS + w * EM_ROW_F4 + lane * 25;
    const int4*   tg = tgS + w * TM_ROW_F4 + lane * 9;
    const float4* mk = mkS + w * TM_ROW_F4 + lane * 9;

    int ptag = (lane == 0) ? tg[0].x : tg[-2].w;   // tag[lane*32 - 1] (or tag[0])

    float M00 = 1.f, M01 = 0.f, M02 = 0.f;
    float M10 = 0.f, M11 = 1.f, M12 = 0.f;
    float M20 = 0.f, M21 = 0.f, M22 = 1.f;
    float gold = 0.f;
    int esum = 0;

    float4 eA0 = em[0], eA1 = em[1], eA2 = em[2];
    int4   tA  = tg[0];
    float4 mA  = mk[0];
    if (lane == 0) mA.x = 0.f;     // t==0 is the init step, not a transition

    #pragma unroll 1
    for (int g = 0; g < 8; ++g) {
        float4 eB0 = eA0, eB1 = eA1, eB2 = eA2;
        int4   tB  = tA;
        float4 mB  = mA;
        if (g + 1 < 8) {
            eB0 = em[(g + 1) * 3 + 0];
            eB1 = em[(g + 1) * 3 + 1];
            eB2 = em[(g + 1) * 3 + 2];
            tB  = tg[g + 1];
            mB  = mk[g + 1];
        }

        STEP(eA0.x, eA0.y, eA0.z, tA.x, mA.x);
        STEP(eA0.w, eA1.x, eA1.y, tA.y, mA.y);
        STEP(eA1.z, eA1.w, eA2.x, tA.z, mA.z);
        STEP(eA2.y, eA2.z, eA2.w, tA.w, mA.w);

        // exact renorm: scale by 2^-ex, ex = ilogb(max entry) (all entries > 0)
        float mxa = fmaxf(fmaxf(M00, M01), M02);
        float mxb = fmaxf(fmaxf(M10, M11), M12);
        float mxc = fmaxf(fmaxf(M20, M21), M22);
        float mx  = fmaxf(fmaxf(mxa, mxb), mxc);
        int ex = (__float_as_int(mx) >> 23) - 127;
        float sc = __int_as_float((127 - ex) << 23);
        M00 *= sc; M01 *= sc; M02 *= sc;
        M10 *= sc; M11 *= sc; M12 *= sc;
        M20 *= sc; M21 *= sc; M22 *= sc;
        esum += ex;

        eA0 = eB0; eA1 = eB1; eA2 = eB2; tA = tB; mA = mB;
    }

    // ---- in-warp ordered tree product: M_total = M_0 * M_1 * ... * M_31 ----
    float e = (float)esum;
    #pragma unroll
    for (int s = 1; s < 32; s <<= 1) {
        float Q00 = __shfl_down_sync(0xffffffffu, M00, s);
        float Q01 = __shfl_down_sync(0xffffffffu, M01, s);
        float Q02 = __shfl_down_sync(0xffffffffu, M02, s);
        float Q10 = __shfl_down_sync(0xffffffffu, M10, s);
        float Q11 = __shfl_down_sync(0xffffffffu, M11, s);
        float Q12 = __shfl_down_sync(0xffffffffu, M12, s);
        float Q20 = __shfl_down_sync(0xffffffffu, M20, s);
        float Q21 = __shfl_down_sync(0xffffffffu, M21, s);
        float Q22 = __shfl_down_sync(0xffffffffu, M22, s);
        float eq  = __shfl_down_sync(0xffffffffu, e,   s);
        float gq  = __shfl_down_sync(0xffffffffu, gold, s);

        float q00 = fmaf(M02, Q20, fmaf(M01, Q10, M00 * Q00));
        float q01 = fmaf(M02, Q21, fmaf(M01, Q11, M00 * Q01));
        float q02 = fmaf(M02, Q22, fmaf(M01, Q12, M00 * Q02));
        float q10 = fmaf(M12, Q20, fmaf(M11, Q10, M10 * Q00));
        float q11 = fmaf(M12, Q21, fmaf(M11, Q11, M10 * Q01));
        float q12 = fmaf(M12, Q22, fmaf(M11, Q12, M10 * Q02));
        float q20 = fmaf(M22, Q20, fmaf(M21, Q10, M20 * Q00));
        float q21 = fmaf(M22, Q21, fmaf(M21, Q11, M20 * Q01));
        float q22 = fmaf(M22, Q22, fmaf(M21, Q12, M20 * Q02));

        float mxa = fmaxf(fmaxf(q00, q01), q02);
        float mxb = fmaxf(fmaxf(q10, q11), q12);
        float mxc = fmaxf(fmaxf(q20, q21), q22);
        float mx  = fmaxf(fmaxf(mxa, mxb), mxc);
        int ex = (__float_as_int(mx) >> 23) - 127;
        float sc = __int_as_float((127 - ex) << 23);
        M00 = q00 * sc; M01 = q01 * sc; M02 = q02 * sc;
        M10 = q10 * sc; M11 = q11 * sc; M12 = q12 * sc;
        M20 = q20 * sc; M21 = q21 * sc; M22 = q22 * sc;

        e += eq + (float)ex;
        gold += gq;
    }

    if (lane == 0) {
        float4 e0 = emS[w * EM_ROW_F4];            // em[b][0][0..2]
        float a0 = __expf(e0.x), a1 = __expf(e0.y), a2 = __expf(e0.z);
        float v0 = fmaf(a2, M20, fmaf(a1, M10, a0 * M00));
        float v1 = fmaf(a2, M21, fmaf(a1, M11, a0 * M01));
        float v2 = fmaf(a2, M22, fmaf(a1, M12, a0 * M02));
        float m0 = mkS[w * TM_ROW_F4].x;           // mask[b][0]
        int   t0 = tgS[w * TM_ROW_F4].x;           // tag[b][0]
        float em0t = (t0 == 0) ? e0.x : ((t0 == 1) ? e0.y : e0.z);
        gold += m0 * em0t;
        float logZ = __logf(v0 + v1 + v2) + e * LN2F;
        sred[w] = logZ - gold;
    }
    __syncthreads();
    if (tid == 0)
        g_partials[blockIdx.x] = (sred[0] + sred[1]) + (sred[2] + sred[3]);
}

__global__ void __launch_bounds__(1024)
crf_final_kernel(float* __restrict__ out)
{
    __shared__ float red[1024];
    int t = threadIdx.x;
    red[t] = g_partials[t] + g_partials[t + 1024];
    __syncthreads();
    #pragma unroll
    for (int s = 512; s > 0; s >>= 1) {
        if (t < s) red[t] += red[t + s];
        __syncthreads();
    }
    if (t == 0) out[0] = red[0] * (1.0f / (float)B_DIM);
}

extern "C" void kernel_launch(void* const* d_in, const int* in_sizes, int n_in,
                              void* d_out, int out_size)
{
    const float* emissions   = (const float*)d_in[0];
    const float* mask        = (const float*)d_in[1];
    const float* transitions = (const float*)d_in[2];
    const int*   tags        = (const int*)d_in[3];
    float* out = (float*)d_out;

    cudaFuncSetAttribute(crf_main_kernel,
                         cudaFuncAttributeMaxDynamicSharedMemorySize, SMEM_BYTES);
    crf_main_kernel<<<NBLOCKS, THREADS, SMEM_BYTES>>>(emissions, mask, transitions, tags);
    crf_final_kernel<<<1, 1024>>>(out);
}

// round 5
// speedup vs baseline: 1.4162x; 1.0595x over previous
#include <cuda_runtime.h>
#include <cstdint>

// LinearCRF: out = mean_b( logZ_b - gold_b )
// 256 threads/block, 4 rows/block, 2 warps per row (half-row each),
// lane = 16 consecutive steps. Emissions staged via cp.async into a
// transposed conflict-free smem layout; tags+mask packed to 1 byte/step.
// Linear-domain 3x3 transfer matrices with exact pow2 renorm; in-warp
// shuffle tree + cross-warp half combine; last-block final reduction.

#define B_DIM   8192
#define L_DIM   1024
#define RPB     4
#define THREADS 256
#define NBLOCKS (B_DIM / RPB)      // 2048
#define LN2F 0.69314718055994530942f

// dynamic smem: em 4*768 float4 (49152 B) + codes 4*256 u32 (4096 B)
#define EM_F4_PER_ROW 768
#define SMEM_BYTES (RPB * EM_F4_PER_ROW * 16 + RPB * 256 * 4)

__device__ float g_partials[NBLOCKS];
__device__ int   g_count = 0;

__device__ __forceinline__ void cp16(uint32_t saddr, const void* gaddr) {
    asm volatile("cp.async.cg.shared.global [%0], [%1], 16;" :: "r"(saddr), "l"(gaddr));
}

// One forward step, code byte cb = tag | (mask?4:0).
//   Mnew[i][j] = (sum_k M[i][k] * E[k][j]) * w_j,  w_j = exp(em_t[j])
// cb<4 (mask==0) => identity step, no gold term.
#define STEP(e0v, e1v, e2v, cbv) do {                                       \
    unsigned cb_ = (cbv);                                                   \
    float w0 = __expf(e0v), w1 = __expf(e1v), w2 = __expf(e2v);             \
    float F00 = E00 * w0, F01 = E01 * w1, F02 = E02 * w2;                   \
    float F10 = E10 * w0, F11 = E11 * w1, F12 = E12 * w2;                   \
    float F20 = E20 * w0, F21 = E21 * w1, F22 = E22 * w2;                   \
    float n00 = fmaf(M02, F20, fmaf(M01, F10, M00 * F00));                  \
    float n01 = fmaf(M02, F21, fmaf(M01, F11, M00 * F01));                  \
    float n02 = fmaf(M02, F22, fmaf(M01, F12, M00 * F02));                  \
    float n10 = fmaf(M12, F20, fmaf(M11, F10, M10 * F00));                  \
    float n11 = fmaf(M12, F21, fmaf(M11, F11, M10 * F01));                  \
    float n12 = fmaf(M12, F22, fmaf(M11, F12, M10 * F02));                  \
    float n20 = fmaf(M22, F20, fmaf(M21, F10, M20 * F00));                  \
    float n21 = fmaf(M22, F21, fmaf(M21, F11, M20 * F01));                  \
    float n22 = fmaf(M22, F22, fmaf(M21, F12, M20 * F02));                  \
    bool u = cb_ >= 4u;                                                     \
    M00 = u ? n00 : M00; M01 = u ? n01 : M01; M02 = u ? n02 : M02;          \
    M10 = u ? n10 : M10; M11 = u ? n11 : M11; M12 = u ? n12 : M12;          \
    M20 = u ? n20 : M20; M21 = u ? n21 : M21; M22 = u ? n22 : M22;          \
    int tgl = (int)(cb_ & 3u);                                              \
    float etg = (tgl == 0) ? (e0v) : ((tgl == 1) ? (e1v) : (e2v));          \
    float add = sT[ptag * 3 + tgl] + etg;                                   \
    gold += u ? add : 0.f;                                                  \
    ptag = tgl;                                                             \
} while (0)

#define RENORM() do {                                                       \
    float mxa = fmaxf(fmaxf(M00, M01), M02);                                \
    float mxb = fmaxf(fmaxf(M10, M11), M12);                                \
    float mxc = fmaxf(fmaxf(M20, M21), M22);                                \
    float mx  = fmaxf(fmaxf(mxa, mxb), mxc);                                \
    int ex = (__float_as_int(mx) >> 23) - 127;                              \
    float sc = __int_as_float((127 - ex) << 23);                            \
    M00 *= sc; M01 *= sc; M02 *= sc;                                        \
    M10 *= sc; M11 *= sc; M12 *= sc;                                        \
    M20 *= sc; M21 *= sc; M22 *= sc;                                        \
    esum += ex;                                                             \
} while (0)

#define GROUP(Ea, Eb, Ec, CW) do {                                          \
    STEP(Ea.x, Ea.y, Ea.z, (CW) & 0xffu);                                   \
    STEP(Ea.w, Eb.x, Eb.y, ((CW) >> 8) & 0xffu);                            \
    STEP(Eb.z, Eb.w, Ec.x, ((CW) >> 16) & 0xffu);                           \
    STEP(Ec.y, Ec.z, Ec.w, (CW) >> 24);                                     \
    RENORM();                                                               \
} while (0)

__global__ void __launch_bounds__(THREADS)
crf_main_kernel(const float* __restrict__ emissions,
                const float* __restrict__ mask,
                const float* __restrict__ transitions,
                const int*   __restrict__ tags,
                float* __restrict__ out)
{
    extern __shared__ char smem[];
    float4*   emS    = (float4*)smem;
    unsigned* codesS = (unsigned*)(smem + RPB * EM_F4_PER_ROW * 16);
    __shared__ float sT[9];
    __shared__ float sHalf[8][11];
    __shared__ float srow[RPB];
    __shared__ int   sLast;

    const int tid  = threadIdx.x;
    const int lane = tid & 31;
    const int w    = tid >> 5;      // 0..7
    const int r    = w >> 1;        // local row
    const int h    = w & 1;         // half
    const int row0 = blockIdx.x * RPB;

    if (tid < 9) sT[tid] = transitions[tid];

    uint32_t emS_a = (uint32_t)__cvta_generic_to_shared(emS);

    // ---- stage emissions: gmem-linear f4 -> smem transposed (j*64 + owner) ----
    const float4* emG = (const float4*)emissions + (size_t)row0 * 768;
    #pragma unroll
    for (int rr = 0; rr < RPB; ++rr) {
        #pragma unroll
        for (int i = 0; i < 3; ++i) {
            int k = tid + i * THREADS;              // 0..767
            int o = k / 12, j = k - o * 12;
            cp16(emS_a + (uint32_t)((rr * EM_F4_PER_ROW + j * 64 + o) << 4),
                 emG + (size_t)rr * 768 + k);
        }
    }
    asm volatile("cp.async.commit_group;");

    // ---- pack tags+mask into code bytes (coalesced LDG, linear STS) ----
    const int4*   tgG = (const int4*)tags + (size_t)row0 * 256;
    const float4* mkG = (const float4*)mask + (size_t)row0 * 256;
    #pragma unroll
    for (int rr = 0; rr < RPB; ++rr) {
        int4   tg = tgG[(size_t)rr * 256 + tid];
        float4 mk = mkG[(size_t)rr * 256 + tid];
        unsigned cw = ((unsigned)(tg.x & 3) | (mk.x > 0.f ? 4u : 0u))
                    | (((unsigned)(tg.y & 3) | (mk.y > 0.f ? 4u : 0u)) << 8)
                    | (((unsigned)(tg.z & 3) | (mk.z > 0.f ? 4u : 0u)) << 16)
                    | (((unsigned)(tg.w & 3) | (mk.w > 0.f ? 4u : 0u)) << 24);
        codesS[rr * 256 + tid] = cw;
    }
    asm volatile("cp.async.wait_group 0;");
    __syncthreads();

    float E00 = __expf(sT[0]), E01 = __expf(sT[1]), E02 = __expf(sT[2]);
    float E10 = __expf(sT[3]), E11 = __expf(sT[4]), E12 = __expf(sT[5]);
    float E20 = __expf(sT[6]), E21 = __expf(sT[7]), E22 = __expf(sT[8]);

    // ---- per-lane 16 steps ----
    const int o = h * 32 + lane;                    // owner 0..63 within row
    const float4* em = emS + r * EM_F4_PER_ROW + o; // access em[(3g+u)*64]
    int4 c4 = ((const int4*)codesS)[r * 64 + o];
    if (h == 0 && lane == 0) c4.x &= ~4;            // step 0 = init, not a transition

    // ptag = tag at (chunk start - 1); lane0 reads smem byte, others shfl
    unsigned prevw = __shfl_up_sync(0xffffffffu, (unsigned)c4.w, 1);
    int ptag;
    if (lane == 0) {
        const unsigned char* cbp = (const unsigned char*)codesS;
        int bi = r * 1024 + h * 512;
        ptag = (h ? cbp[bi - 1] : cbp[bi]) & 3;
    } else {
        ptag = (int)((prevw >> 24) & 3u);
    }

    float M00 = 1.f, M01 = 0.f, M02 = 0.f;
    float M10 = 0.f, M11 = 1.f, M12 = 0.f;
    float M20 = 0.f, M21 = 0.f, M22 = 1.f;
    float gold = 0.f;
    int esum = 0;

    float4 e0a = em[0 * 64],  e0b = em[1 * 64],  e0c = em[2 * 64];
    float4 e1a = em[3 * 64],  e1b = em[4 * 64],  e1c = em[5 * 64];
    GROUP(e0a, e0b, e0c, (unsigned)c4.x);
    float4 e2a = em[6 * 64],  e2b = em[7 * 64],  e2c = em[8 * 64];
    GROUP(e1a, e1b, e1c, (unsigned)c4.y);
    float4 e3a = em[9 * 64],  e3b = em[10 * 64], e3c = em[11 * 64];
    GROUP(e2a, e2b, e2c, (unsigned)c4.z);
    GROUP(e3a, e3b, e3c, (unsigned)c4.w);

    // ---- in-warp ordered tree product over the 32 lane chunks ----
    float e = (float)esum;
    #pragma unroll
    for (int s = 1; s < 32; s <<= 1) {
        float Q00 = __shfl_down_sync(0xffffffffu, M00, s);
        float Q01 = __shfl_down_sync(0xffffffffu, M01, s);
        float Q02 = __shfl_down_sync(0xffffffffu, M02, s);
        float Q10 = __shfl_down_sync(0xffffffffu, M10, s);
        float Q11 = __shfl_down_sync(0xffffffffu, M11, s);
        float Q12 = __shfl_down_sync(0xffffffffu, M12, s);
        float Q20 = __shfl_down_sync(0xffffffffu, M20, s);
        float Q21 = __shfl_down_sync(0xffffffffu, M21, s);
        float Q22 = __shfl_down_sync(0xffffffffu, M22, s);
        float eq  = __shfl_down_sync(0xffffffffu, e,   s);
        float gq  = __shfl_down_sync(0xffffffffu, gold, s);

        float q00 = fmaf(M02, Q20, fmaf(M01, Q10, M00 * Q00));
        float q01 = fmaf(M02, Q21, fmaf(M01, Q11, M00 * Q01));
        float q02 = fmaf(M02, Q22, fmaf(M01, Q12, M00 * Q02));
        float q10 = fmaf(M12, Q20, fmaf(M11, Q10, M10 * Q00));
        float q11 = fmaf(M12, Q21, fmaf(M11, Q11, M10 * Q01));
        float q12 = fmaf(M12, Q22, fmaf(M11, Q12, M10 * Q02));
        float q20 = fmaf(M22, Q20, fmaf(M21, Q10, M20 * Q00));
        float q21 = fmaf(M22, Q21, fmaf(M21, Q11, M20 * Q01));
        float q22 = fmaf(M22, Q22, fmaf(M21, Q12, M20 * Q02));

        float mxa = fmaxf(fmaxf(q00, q01), q02);
        float mxb = fmaxf(fmaxf(q10, q11), q12);
        float mxc = fmaxf(fmaxf(q20, q21), q22);
        float mx  = fmaxf(fmaxf(mxa, mxb), mxc);
        int ex = (__float_as_int(mx) >> 23) - 127;
        float sc = __int_as_float((127 - ex) << 23);
        M00 = q00 * sc; M01 = q01 * sc; M02 = q02 * sc;
        M10 = q10 * sc; M11 = q11 * sc; M12 = q12 * sc;
        M20 = q20 * sc; M21 = q21 * sc; M22 = q22 * sc;

        e += eq + (float)ex;
        gold += gq;
    }

    if (lane == 0) {
        float* dst = sHalf[w];
        dst[0] = M00; dst[1] = M01; dst[2] = M02;
        dst[3] = M10; dst[4] = M11; dst[5] = M12;
        dst[6] = M20; dst[7] = M21; dst[8] = M22;
        dst[9] = e;   dst[10] = gold;
    }
    __syncthreads();

    // ---- per-row: alpha0 * H0 * H1, logZ, gold base term ----
    if (tid < RPB) {
        int rr = tid;
        const float* A = sHalf[rr * 2];
        const float* Bm = sHalf[rr * 2 + 1];

        float4 e0 = emS[rr * EM_F4_PER_ROW];      // em[row][0][0..2] (+extra)
        float a0 = __expf(e0.x), a1 = __expf(e0.y), a2 = __expf(e0.z);
        // v = alpha0 * H0
        float u0 = fmaf(a2, A[6], fmaf(a1, A[3], a0 * A[0]));
        float u1 = fmaf(a2, A[7], fmaf(a1, A[4], a0 * A[1]));
        float u2 = fmaf(a2, A[8], fmaf(a1, A[5], a0 * A[2]));
        // v = v * H1
        float v0 = fmaf(u2, Bm[6], fmaf(u1, Bm[3], u0 * Bm[0]));
        float v1 = fmaf(u2, Bm[7], fmaf(u1, Bm[4], u0 * Bm[1]));
        float v2 = fmaf(u2, Bm[8], fmaf(u1, Bm[5], u0 * Bm[2]));

        float esumT = A[9] + Bm[9];
        float goldT = A[10] + Bm[10];

        unsigned c0 = codesS[rr * 256];
        int   t0 = (int)(c0 & 3u);
        float m0 = (float)((c0 >> 2) & 1u);
        float em0t = (t0 == 0) ? e0.x : ((t0 == 1) ? e0.y : e0.z);
        goldT += m0 * em0t;

        float logZ = __logf(v0 + v1 + v2) + esumT * LN2F;
        srow[rr] = logZ - goldT;
    }
    __syncthreads();

    if (tid == 0) {
        g_partials[blockIdx.x] = (srow[0] + srow[1]) + (srow[2] + srow[3]);
        __threadfence();
        int tk = atomicAdd(&g_count, 1);
        sLast = (tk == NBLOCKS - 1);
    }
    __syncthreads();

    // ---- last block: fixed-order final reduction ----
    if (sLast) {
        float s = 0.f;
        #pragma unroll
        for (int i = 0; i < NBLOCKS / THREADS; ++i)
            s += __ldcg(&g_partials[tid * (NBLOCKS / THREADS) + i]);
        float* red = (float*)smem;                // reuse staging smem
        red[tid] = s;
        __syncthreads();
        #pragma unroll
        for (int st = THREADS / 2; st > 0; st >>= 1) {
            if (tid < st) red[tid] += red[tid + st];
            __syncthreads();
        }
        if (tid == 0) {
            out[0] = red[0] * (1.0f / (float)B_DIM);
            g_count = 0;                          // reset for next graph replay
        }
    }
}

extern "C" void kernel_launch(void* const* d_in, const int* in_sizes, int n_in,
                              void* d_out, int out_size)
{
    const float* emissions   = (const float*)d_in[0];
    const float* mask        = (const float*)d_in[1];
    const float* transitions = (const float*)d_in[2];
    const int*   tags        = (const int*)d_in[3];
    float* out = (float*)d_out;

    cudaFuncSetAttribute(crf_main_kernel,
                         cudaFuncAttributeMaxDynamicSharedMemorySize, SMEM_BYTES);
    crf_main_kernel<<<NBLOCKS, THREADS, SMEM_BYTES>>>(emissions, mask, transitions,
                                                      tags, out);
}